// round 11
// baseline (speedup 1.0000x reference)
#include <cuda_runtime.h>
#include <math.h>

typedef unsigned long long ull;

// ---------------------------------------------------------------------------
// Scratch (device globals; allocations forbidden).
// ---------------------------------------------------------------------------
#define VS 345600
#define PS 1881600
__device__ float g_bufA[3 * VS];
__device__ float g_bufB[3 * VS];
__device__ float g_patch[3 * PS];   // streams: center | mid | rad
__device__ float g_wpad[96 * 148];

#define ABSM 0x7FFFFFFF7FFFFFFFULL
#define M1   0xBF800000BF800000ULL

// ---------------------------------------------------------------------------
// f32x2 packed helpers (sm_103a)
// ---------------------------------------------------------------------------
__device__ __forceinline__ ull pk2(float lo, float hi) {
    ull r; asm("mov.b64 %0, {%1,%2};" : "=l"(r) : "f"(lo), "f"(hi)); return r;
}
__device__ __forceinline__ void upk2(ull v, float& lo, float& hi) {
    asm("mov.b64 {%0,%1}, %2;" : "=f"(lo), "=f"(hi) : "l"(v));
}
__device__ __forceinline__ ull fma2(ull a, ull b, ull c) {
    ull r; asm("fma.rn.f32x2 %0, %1, %2, %3;" : "=l"(r) : "l"(a), "l"(b), "l"(c)); return r;
}
__device__ __forceinline__ ull mul2(ull a, ull b) {
    ull r; asm("mul.rn.f32x2 %0, %1, %2;" : "=l"(r) : "l"(a), "l"(b)); return r;
}
__device__ __forceinline__ ull add2(ull a, ull b) {
    ull r; asm("add.rn.f32x2 %0, %1, %2;" : "=l"(r) : "l"(a), "l"(b)); return r;
}
__device__ __forceinline__ float root8(float s) { return sqrtf(sqrtf(sqrtf(s))); }

// All-packed bound-distance accumulation.
// a = mid - w;  dh = |a|+rad;  v = 2*relu(|a|-rad);  dc = vc - w.
// AL accumulates (2*dl)^8 -> epilogue multiplies root8 by 0.5 (exact).
#define HALF(W, VC, MD, RD, AC, AL, AH) {                               \
        ull dc = fma2(W, M1, VC);                                       \
        ull s  = mul2(dc, dc); s = mul2(s, s); AC = fma2(s, s, AC);     \
        ull a  = fma2(W, M1, MD);                                       \
        ull aa = a & ABSM;                                              \
        ull dh = add2(aa, RD);                                          \
        s = mul2(dh, dh); s = mul2(s, s); AH = fma2(s, s, AH);          \
        ull t  = fma2(RD, M1, aa);                                      \
        ull v  = add2(t, t & ABSM);                                     \
        s = mul2(v, v); s = mul2(s, s); AL = fma2(s, s, AL); }

// ---------------------------------------------------------------------------
// prep1: conv1 im2col of (center, mid, rad) from real lower/upper inputs
// (Fp 147->148 zero-pad) + conv1 weight pad.
// ---------------------------------------------------------------------------
#define P1_IM2COL (16 * 225 * 148)
#define P1_WPAD   (96 * 148)
__global__ void __launch_bounds__(256) prep1_kernel(
    const float* __restrict__ ic, const float* __restrict__ il, const float* __restrict__ ih,
    const float* __restrict__ w1,
    float* __restrict__ oc, float* __restrict__ om, float* __restrict__ orr,
    float* __restrict__ wp)
{
    const int idx = blockIdx.x * blockDim.x + threadIdx.x;
    if (idx < P1_IM2COL) {
        const int f  = idx % 148;
        const int bl = idx / 148;
        const int l  = bl % 225;
        const int b  = bl / 225;
        float vc = 0.f, vm = 0.f, vr = 0.f;
        if (f < 147) {
            const int c  = f / 49;
            const int r  = f - c * 49;
            const int ky = r / 7, kx = r - (r / 7) * 7;
            const int oy = l / 15, ox = l - (l / 15) * 15;
            const int iy = oy * 2 - 2 + ky;
            const int ix = ox * 2 - 2 + kx;
            if ((unsigned)iy < 32u && (unsigned)ix < 32u) {
                const int si = ((b * 3 + c) * 32 + iy) * 32 + ix;
                const float lv = il[si], hv = ih[si];
                vc = ic[si]; vm = 0.5f * (lv + hv); vr = 0.5f * (hv - lv);
            }
        }
        oc[idx] = vc; om[idx] = vm; orr[idx] = vr;
    } else if (idx < P1_IM2COL + P1_WPAD) {
        const int j = idx - P1_IM2COL;
        const int f = j % 148, o = j / 148;
        wp[j] = (f < 147) ? w1[o * 147 + f] : 0.f;
    }
}

// ---------------------------------------------------------------------------
// 3x3/s2 maxpool on (c, l, h) -> compact (c, mid, rad) [B,C,h,w].
// ---------------------------------------------------------------------------
__global__ void __launch_bounds__(256) pool3s_kernel(
    const float* __restrict__ ic, const float* __restrict__ il, const float* __restrict__ ih,
    float* __restrict__ oc, float* __restrict__ om, float* __restrict__ orr,
    int NC, int H, int W, int h, int w)
{
    const int i = blockIdx.x * blockDim.x + threadIdx.x;
    if (i >= NC * h * w) return;
    const int x = i % w;
    const int y = (i / w) % h;
    const int n = i / (w * h);
    const int base = (n * H + y * 2) * W + x * 2;
    float m0 = -3.402823466e38f, m1 = m0, m2 = m0;
#pragma unroll
    for (int ky = 0; ky < 3; ky++)
#pragma unroll
        for (int kx = 0; kx < 3; kx++) {
            const int si = base + ky * W + kx;
            m0 = fmaxf(m0, ic[si]);
            m1 = fmaxf(m1, il[si]);
            m2 = fmaxf(m2, ih[si]);
        }
    oc[i] = m0; om[i] = 0.5f * (m1 + m2); orr[i] = 0.5f * (m2 - m1);
}

// ---------------------------------------------------------------------------
// Pure gather im2col: compact (c,m,r) [B,C,h,w] -> patch streams.
// ---------------------------------------------------------------------------
__global__ void __launch_bounds__(256) gather_kernel(
    const float* __restrict__ ic, const float* __restrict__ im, const float* __restrict__ ir,
    float* __restrict__ oc, float* __restrict__ om, float* __restrict__ orr,
    int B, int C, int h, int w, int K, int pad)
{
    const int Fp = C * K * K;
    const int L  = h * w;
    const int idx = blockIdx.x * blockDim.x + threadIdx.x;
    if (idx >= B * L * Fp) return;
    const int f  = idx % Fp;
    const int bl = idx / Fp;
    const int l  = bl % L;
    const int b  = bl / L;
    const int c  = f / (K * K);
    const int r  = f - c * (K * K);
    const int ky = r / K, kx = r - (r / K) * K;
    const int oy = l / w, ox = l - (l / w) * w;
    const int py = oy - pad + ky;
    const int px = ox - pad + kx;
    float vc = 0.f, vm = 0.f, vr = 0.f;
    if ((unsigned)py < (unsigned)h && (unsigned)px < (unsigned)w) {
        const int si = ((b * C + c) * h + py) * w + px;
        vc = ic[si]; vm = im[si]; vr = ir[si];
    }
    oc[idx] = vc; om[idx] = vm; orr[idx] = vr;
}

// ---------------------------------------------------------------------------
// Packed NormDist (L8) conv: block = 8 warps, 1 og-quad of weights in smem,
// 8 bl per block. grid = (O/4, BL/8). Patch loads double-buffered to hide
// L2 latency (pipe was 79% busy; stalls were the gap).
// outmode 0: write (c, ol, oh);  outmode 1: write (c, mid, rad).
// ---------------------------------------------------------------------------
__global__ void __launch_bounds__(256, 3) normdist_conv_s_kernel(
    const float* __restrict__ pc, const float* __restrict__ pm, const float* __restrict__ pr,
    const float* __restrict__ wgt,
    float* __restrict__ o0, float* __restrict__ o1, float* __restrict__ o2,
    int Fp, int L, int O, int outmode)
{
    extern __shared__ float sw[];
    const int tid = threadIdx.x;
    {
        const float4* src = (const float4*)(wgt + (size_t)blockIdx.x * 4 * Fp);
        float4* dst = (float4*)sw;
        for (int i = tid; i < Fp; i += 256) dst[i] = src[i];
    }
    __syncthreads();

    const int w    = tid >> 5;
    const int lane = tid & 31;
    const int bl   = blockIdx.y * 8 + w;
    const int fs   = Fp >> 2;

    const float4* pc4 = (const float4*)(pc + (size_t)bl * Fp);
    const float4* pm4 = (const float4*)(pm + (size_t)bl * Fp);
    const float4* pr4 = (const float4*)(pr + (size_t)bl * Fp);
    const float4* wq  = (const float4*)sw;

    ull A[12];
#pragma unroll
    for (int i = 0; i < 12; i++) A[i] = 0;

    // software pipeline: prefetch next chunk before computing current
    int q = lane;
    float4 cc, cm, cr;
    if (q < fs) { cc = pc4[q]; cm = pm4[q]; cr = pr4[q]; }
    while (q < fs) {
        const int qn = q + 32;
        float4 nc, nm, nr;
        if (qn < fs) { nc = pc4[qn]; nm = pm4[qn]; nr = pr4[qn]; }
        const ull c01 = pk2(cc.x, cc.y), c23 = pk2(cc.z, cc.w);
        const ull m01 = pk2(cm.x, cm.y), m23 = pk2(cm.z, cm.w);
        const ull r01 = pk2(cr.x, cr.y), r23 = pk2(cr.z, cr.w);
#pragma unroll
        for (int ch = 0; ch < 4; ch++) {
            const float4 wv = wq[q + ch * fs];
            const ull w01 = pk2(wv.x, wv.y), w23 = pk2(wv.z, wv.w);
            HALF(w01, c01, m01, r01, A[ch * 3], A[ch * 3 + 1], A[ch * 3 + 2]);
            HALF(w23, c23, m23, r23, A[ch * 3], A[ch * 3 + 1], A[ch * 3 + 2]);
        }
        cc = nc; cm = nm; cr = nr;
        q = qn;
    }

    float r[12];
#pragma unroll
    for (int i = 0; i < 12; i++) {
        float x0, x1; upk2(A[i], x0, x1); r[i] = x0 + x1;
    }
#pragma unroll
    for (int off = 16; off; off >>= 1)
#pragma unroll
        for (int i = 0; i < 12; i++)
            r[i] += __shfl_xor_sync(0xffffffffu, r[i], off);

    if (lane < 4) {
        const int b = bl / L, l = bl - (bl / L) * L;
        const int o = blockIdx.x * 4 + lane;
        const size_t ob = ((size_t)b * O + o) * L + l;
        const float oc = root8(r[3 * lane]);
        const float ol = 0.5f * root8(r[3 * lane + 1]);
        const float oh = root8(r[3 * lane + 2]);
        o0[ob] = oc;
        if (outmode == 0) { o1[ob] = ol; o2[ob] = oh; }
        else              { o1[ob] = 0.5f * (ol + oh); o2[ob] = 0.5f * (oh - ol); }
    }
}

// ---------------------------------------------------------------------------
// Interval-bound linear on (c, m, r) streams, 4 batches per warp.
// mode 0: relu epilogue, outputs (c, m, r); mode 1: final (-c, -u, -l).
// ---------------------------------------------------------------------------
__global__ void __launch_bounds__(256) bound_linear4_kernel(
    const float* __restrict__ inc, const float* __restrict__ inm, const float* __restrict__ inr,
    const float* __restrict__ Wm, const float* __restrict__ bias,
    float* __restrict__ o0, float* __restrict__ o1, float* __restrict__ o2,
    int B, int IN, int OUT, int mode)
{
    const int warp = (blockIdx.x * blockDim.x + threadIdx.x) >> 5;
    const int lane = threadIdx.x & 31;
    const int BG = B >> 2;
    if (warp >= OUT * BG) return;
    const int o  = warp % OUT;
    const int bg = warp / OUT;
    const int b0 = bg * 4;

    const float4* w4 = (const float4*)(Wm + (size_t)o * IN);
    const float4* c4 = (const float4*)(inc + (size_t)b0 * IN);
    const float4* m4 = (const float4*)(inm + (size_t)b0 * IN);
    const float4* r4 = (const float4*)(inr + (size_t)b0 * IN);
    const int n4 = IN >> 2;

    float r[12];
#pragma unroll
    for (int i = 0; i < 12; i++) r[i] = 0.f;

    for (int k = lane; k < n4; k += 32) {
        const float4 wv = w4[k];
        const float awx = fabsf(wv.x), awy = fabsf(wv.y), awz = fabsf(wv.z), aww = fabsf(wv.w);
#pragma unroll
        for (int j = 0; j < 4; j++) {
            const float4 cv = c4[k + (size_t)j * n4];
            const float4 mv = m4[k + (size_t)j * n4];
            const float4 rv = r4[k + (size_t)j * n4];
            float sc = r[j * 3], sm = r[j * 3 + 1], sr = r[j * 3 + 2];
            sc = fmaf(cv.x, wv.x, sc); sc = fmaf(cv.y, wv.y, sc);
            sc = fmaf(cv.z, wv.z, sc); sc = fmaf(cv.w, wv.w, sc);
            sm = fmaf(mv.x, wv.x, sm); sm = fmaf(mv.y, wv.y, sm);
            sm = fmaf(mv.z, wv.z, sm); sm = fmaf(mv.w, wv.w, sm);
            sr = fmaf(rv.x, awx, sr); sr = fmaf(rv.y, awy, sr);
            sr = fmaf(rv.z, awz, sr); sr = fmaf(rv.w, aww, sr);
            r[j * 3] = sc; r[j * 3 + 1] = sm; r[j * 3 + 2] = sr;
        }
    }
#pragma unroll
    for (int off = 16; off; off >>= 1)
#pragma unroll
        for (int i = 0; i < 12; i++)
            r[i] += __shfl_xor_sync(0xffffffffu, r[i], off);

    if (lane < 4) {
        const int b = b0 + lane;
        const float sc = r[lane * 3], sm = r[lane * 3 + 1], sr = r[lane * 3 + 2];
        const size_t idx = (size_t)b * OUT + o;
        if (mode == 0) {
            const float lr = fmaxf(sm - sr, 0.f);
            const float hr = fmaxf(sm + sr, 0.f);
            o0[idx] = fmaxf(sc, 0.f);
            o1[idx] = 0.5f * (lr + hr);
            o2[idx] = 0.5f * (hr - lr);
        } else {
            const float bv  = bias[o];
            const float oc  = sc + bv;
            const float mid = sm + bv;
            o0[idx] = -oc;            // -center
            o1[idx] = -(mid + sr);    // -upper
            o2[idx] = -(mid - sr);    // -lower
        }
    }
}

// ---------------------------------------------------------------------------
// Host orchestration (graph-capturable: launches only).
// ---------------------------------------------------------------------------
static inline int cdiv(int a, int b) { return (a + b - 1) / b; }

extern "C" void kernel_launch(void* const* d_in, const int* in_sizes, int n_in,
                              void* d_out, int out_size)
{
    const float* x   = (const float*)d_in[0];
    const float* lo  = (const float*)d_in[1];
    const float* hi  = (const float*)d_in[2];
    const float* w1  = (const float*)d_in[3];
    const float* w2  = (const float*)d_in[4];
    const float* w3  = (const float*)d_in[5];
    const float* w4  = (const float*)d_in[6];
    const float* w5  = (const float*)d_in[7];
    const float* fw1 = (const float*)d_in[8];
    const float* fw2 = (const float*)d_in[9];
    const float* fw3 = (const float*)d_in[10];
    const float* fb3 = (const float*)d_in[11];
    float* out = (float*)d_out;

    cudaFuncSetAttribute(normdist_conv_s_kernel,
                         cudaFuncAttributeMaxDynamicSharedMemorySize, 56 * 1024);

    float *A, *Bf, *P, *WP;
    cudaGetSymbolAddress((void**)&A,  g_bufA);
    cudaGetSymbolAddress((void**)&Bf, g_bufB);
    cudaGetSymbolAddress((void**)&P,  g_patch);
    cudaGetSymbolAddress((void**)&WP, g_wpad);
    float *A0 = A,  *A1 = A  + VS, *A2 = A  + 2 * VS;
    float *B0 = Bf, *B1 = Bf + VS, *B2 = Bf + 2 * VS;
    float *P0 = P,  *P1 = P  + PS, *P2 = P  + 2 * PS;

#define CONVS(W_, o0, o1, o2, BL_, O_, FP_, L_, MODE_)                              \
    normdist_conv_s_kernel<<<dim3((O_) / 4, (BL_) / 8), 256, 4 * (FP_) * 4>>>(      \
        P0, P1, P2, W_, o0, o1, o2, FP_, L_, O_, MODE_)

    // (1) prep: conv1 patches (c,m,r) from real lower/upper + weight pad
    prep1_kernel<<<cdiv(P1_IM2COL + P1_WPAD, 256), 256>>>(
        x, lo, hi, w1, P0, P1, P2, WP);

    // (2) conv1: -> [16,96,15,15] as (c,ol,oh)
    CONVS(WP, A0, A1, A2, 3600, 96, 148, 225, 0);

    // (3) pool1: -> compact (c,m,r) [16,96,7,7]
    pool3s_kernel<<<cdiv(16 * 96 * 49, 256), 256>>>(
        A0, A1, A2, B0, B1, B2, 16 * 96, 15, 15, 7, 7);

    // (4) gather k=5,p=2: Fp=2400
    gather_kernel<<<cdiv(16 * 49 * 2400, 256), 256>>>(
        B0, B1, B2, P0, P1, P2, 16, 96, 7, 7, 5, 2);

    // (5) conv2: -> [16,256,7,7] as (c,ol,oh)
    CONVS(w2, A0, A1, A2, 784, 256, 2400, 49, 0);

    // (6) pool2: -> compact (c,m,r) [16,256,3,3]
    pool3s_kernel<<<cdiv(16 * 256 * 9, 256), 256>>>(
        A0, A1, A2, B0, B1, B2, 16 * 256, 7, 7, 3, 3);

    // (7) gather k=3,p=1: Fp=2304
    gather_kernel<<<cdiv(16 * 9 * 2304, 256), 256>>>(
        B0, B1, B2, P0, P1, P2, 16, 256, 3, 3, 3, 1);

    // (8) conv3: -> [16,384,3,3] as (c,m,r)
    CONVS(w3, A0, A1, A2, 144, 384, 2304, 9, 1);

    // (9) gather k=3,p=1: Fp=3456
    gather_kernel<<<cdiv(16 * 9 * 3456, 256), 256>>>(
        A0, A1, A2, P0, P1, P2, 16, 384, 3, 3, 3, 1);

    // (10) conv4: -> [16,384,3,3] as (c,m,r)
    CONVS(w4, B0, B1, B2, 144, 384, 3456, 9, 1);

    // (11) gather: Fp=3456
    gather_kernel<<<cdiv(16 * 9 * 3456, 256), 256>>>(
        B0, B1, B2, P0, P1, P2, 16, 384, 3, 3, 3, 1);

    // (12) conv5: -> [16,256,3,3] as (c,m,r) == flattened [16,2304]
    CONVS(w5, A0, A1, A2, 144, 256, 3456, 9, 1);

    // (13) fc1: 2304 -> 1024 (+relu), (c,m,r)
    bound_linear4_kernel<<<cdiv(1024 * 4 * 32, 256), 256>>>(
        A0, A1, A2, fw1, (const float*)nullptr, B0, B1, B2, 16, 2304, 1024, 0);
    // (14) fc2: 1024 -> 512 (+relu)
    bound_linear4_kernel<<<cdiv(512 * 4 * 32, 256), 256>>>(
        B0, B1, B2, fw2, (const float*)nullptr, A0, A1, A2, 16, 1024, 512, 0);
    // (15) fc3: 512 -> 10 (+bias): d_out = [-c | -u | -l]
    bound_linear4_kernel<<<cdiv(10 * 4 * 32, 256), 256>>>(
        A0, A1, A2, fw3, fb3, out, out + 160, out + 320, 16, 512, 10, 1);

#undef CONVS
}

// round 12
// speedup vs baseline: 1.0736x; 1.0736x over previous
#include <cuda_runtime.h>
#include <math.h>

typedef unsigned long long ull;

// ---------------------------------------------------------------------------
// Scratch (device globals; allocations forbidden).
// ---------------------------------------------------------------------------
#define VS 345600
#define PS 1881600
__device__ float g_bufA[3 * VS];
__device__ float g_bufB[3 * VS];
__device__ float g_patch[3 * PS];   // streams: center | mid | rad
__device__ float g_wpad[96 * 148];

#define ABSM 0x7FFFFFFF7FFFFFFFULL
#define M1   0xBF800000BF800000ULL

// ---------------------------------------------------------------------------
// f32x2 packed helpers (sm_103a)
// ---------------------------------------------------------------------------
__device__ __forceinline__ ull pk2(float lo, float hi) {
    ull r; asm("mov.b64 %0, {%1,%2};" : "=l"(r) : "f"(lo), "f"(hi)); return r;
}
__device__ __forceinline__ void upk2(ull v, float& lo, float& hi) {
    asm("mov.b64 {%0,%1}, %2;" : "=f"(lo), "=f"(hi) : "l"(v));
}
__device__ __forceinline__ ull fma2(ull a, ull b, ull c) {
    ull r; asm("fma.rn.f32x2 %0, %1, %2, %3;" : "=l"(r) : "l"(a), "l"(b), "l"(c)); return r;
}
__device__ __forceinline__ ull mul2(ull a, ull b) {
    ull r; asm("mul.rn.f32x2 %0, %1, %2;" : "=l"(r) : "l"(a), "l"(b)); return r;
}
__device__ __forceinline__ ull add2(ull a, ull b) {
    ull r; asm("add.rn.f32x2 %0, %1, %2;" : "=l"(r) : "l"(a), "l"(b)); return r;
}
__device__ __forceinline__ float root8(float s) { return sqrtf(sqrtf(sqrtf(s))); }

// All-packed bound-distance accumulation (13 fma-pipe ops / HALF).
// a = mid - w;  dh = |a|+rad;  dl = relu(|a|-rad) via scalar FMNMX (alu pipe);
// dc = vc - w.
#define HALF(W, VC, MD, RD, AC, AL, AH) {                               \
        ull dc = fma2(W, M1, VC);                                       \
        ull s  = mul2(dc, dc); s = mul2(s, s); AC = fma2(s, s, AC);     \
        ull a  = fma2(W, M1, MD);                                       \
        ull aa = a & ABSM;                                              \
        ull dh = add2(aa, RD);                                          \
        s = mul2(dh, dh); s = mul2(s, s); AH = fma2(s, s, AH);          \
        ull t  = fma2(RD, M1, aa);                                      \
        float t0, t1; upk2(t, t0, t1);                                  \
        ull v  = pk2(fmaxf(t0, 0.f), fmaxf(t1, 0.f));                   \
        s = mul2(v, v); s = mul2(s, s); AL = fma2(s, s, AL); }

// One 4-channel x 4-f-element compute body (weights from smem).
#define BODY(Q, C4, M4, R4) {                                           \
        const ull c01 = pk2(C4.x, C4.y), c23 = pk2(C4.z, C4.w);         \
        const ull m01 = pk2(M4.x, M4.y), m23 = pk2(M4.z, M4.w);         \
        const ull r01 = pk2(R4.x, R4.y), r23 = pk2(R4.z, R4.w);         \
        _Pragma("unroll")                                               \
        for (int ch = 0; ch < 4; ch++) {                                \
            const float4 wv = wq[(Q) + ch * fs];                        \
            const ull w01 = pk2(wv.x, wv.y), w23 = pk2(wv.z, wv.w);     \
            HALF(w01, c01, m01, r01, A[ch*3], A[ch*3+1], A[ch*3+2]);    \
            HALF(w23, c23, m23, r23, A[ch*3], A[ch*3+1], A[ch*3+2]);    \
        } }

// ---------------------------------------------------------------------------
// prep1: conv1 im2col of (center, mid, rad) from real lower/upper inputs
// (Fp 147->148 zero-pad) + conv1 weight pad.
// ---------------------------------------------------------------------------
#define P1_IM2COL (16 * 225 * 148)
#define P1_WPAD   (96 * 148)
__global__ void __launch_bounds__(256) prep1_kernel(
    const float* __restrict__ ic, const float* __restrict__ il, const float* __restrict__ ih,
    const float* __restrict__ w1,
    float* __restrict__ oc, float* __restrict__ om, float* __restrict__ orr,
    float* __restrict__ wp)
{
    const int idx = blockIdx.x * blockDim.x + threadIdx.x;
    if (idx < P1_IM2COL) {
        const int f  = idx % 148;
        const int bl = idx / 148;
        const int l  = bl % 225;
        const int b  = bl / 225;
        float vc = 0.f, vm = 0.f, vr = 0.f;
        if (f < 147) {
            const int c  = f / 49;
            const int r  = f - c * 49;
            const int ky = r / 7, kx = r - (r / 7) * 7;
            const int oy = l / 15, ox = l - (l / 15) * 15;
            const int iy = oy * 2 - 2 + ky;
            const int ix = ox * 2 - 2 + kx;
            if ((unsigned)iy < 32u && (unsigned)ix < 32u) {
                const int si = ((b * 3 + c) * 32 + iy) * 32 + ix;
                const float lv = il[si], hv = ih[si];
                vc = ic[si]; vm = 0.5f * (lv + hv); vr = 0.5f * (hv - lv);
            }
        }
        oc[idx] = vc; om[idx] = vm; orr[idx] = vr;
    } else if (idx < P1_IM2COL + P1_WPAD) {
        const int j = idx - P1_IM2COL;
        const int f = j % 148, o = j / 148;
        wp[j] = (f < 147) ? w1[o * 147 + f] : 0.f;
    }
}

// ---------------------------------------------------------------------------
// 3x3/s2 maxpool on (c, l, h) -> compact (c, mid, rad) [B,C,h,w].
// ---------------------------------------------------------------------------
__global__ void __launch_bounds__(256) pool3s_kernel(
    const float* __restrict__ ic, const float* __restrict__ il, const float* __restrict__ ih,
    float* __restrict__ oc, float* __restrict__ om, float* __restrict__ orr,
    int NC, int H, int W, int h, int w)
{
    const int i = blockIdx.x * blockDim.x + threadIdx.x;
    if (i >= NC * h * w) return;
    const int x = i % w;
    const int y = (i / w) % h;
    const int n = i / (w * h);
    const int base = (n * H + y * 2) * W + x * 2;
    float m0 = -3.402823466e38f, m1 = m0, m2 = m0;
#pragma unroll
    for (int ky = 0; ky < 3; ky++)
#pragma unroll
        for (int kx = 0; kx < 3; kx++) {
            const int si = base + ky * W + kx;
            m0 = fmaxf(m0, ic[si]);
            m1 = fmaxf(m1, il[si]);
            m2 = fmaxf(m2, ih[si]);
        }
    oc[i] = m0; om[i] = 0.5f * (m1 + m2); orr[i] = 0.5f * (m2 - m1);
}

// ---------------------------------------------------------------------------
// Pure gather im2col: compact (c,m,r) [B,C,h,w] -> patch streams.
// ---------------------------------------------------------------------------
__global__ void __launch_bounds__(256) gather_kernel(
    const float* __restrict__ ic, const float* __restrict__ im, const float* __restrict__ ir,
    float* __restrict__ oc, float* __restrict__ om, float* __restrict__ orr,
    int B, int C, int h, int w, int K, int pad)
{
    const int Fp = C * K * K;
    const int L  = h * w;
    const int idx = blockIdx.x * blockDim.x + threadIdx.x;
    if (idx >= B * L * Fp) return;
    const int f  = idx % Fp;
    const int bl = idx / Fp;
    const int l  = bl % L;
    const int b  = bl / L;
    const int c  = f / (K * K);
    const int r  = f - c * (K * K);
    const int ky = r / K, kx = r - (r / K) * K;
    const int oy = l / w, ox = l - (l / w) * w;
    const int py = oy - pad + ky;
    const int px = ox - pad + kx;
    float vc = 0.f, vm = 0.f, vr = 0.f;
    if ((unsigned)py < (unsigned)h && (unsigned)px < (unsigned)w) {
        const int si = ((b * C + c) * h + py) * w + px;
        vc = ic[si]; vm = im[si]; vr = ir[si];
    }
    oc[idx] = vc; om[idx] = vm; orr[idx] = vr;
}

// ---------------------------------------------------------------------------
// Packed NormDist (L8) conv: block = 8 warps, 1 og-quad of weights in smem,
// 8 bl per block. grid = (O/4, BL/8). Unroll-2 over f-chunks with the 6
// patch loads batched at the top (MLP=6 -> half the exposed L2 latency).
// outmode 0: write (c, ol, oh);  outmode 1: write (c, mid, rad).
// ---------------------------------------------------------------------------
__global__ void __launch_bounds__(256, 3) normdist_conv_s_kernel(
    const float* __restrict__ pc, const float* __restrict__ pm, const float* __restrict__ pr,
    const float* __restrict__ wgt,
    float* __restrict__ o0, float* __restrict__ o1, float* __restrict__ o2,
    int Fp, int L, int O, int outmode)
{
    extern __shared__ float sw[];
    const int tid = threadIdx.x;
    {
        const float4* src = (const float4*)(wgt + (size_t)blockIdx.x * 4 * Fp);
        float4* dst = (float4*)sw;
        for (int i = tid; i < Fp; i += 256) dst[i] = src[i];
    }
    __syncthreads();

    const int w    = tid >> 5;
    const int lane = tid & 31;
    const int bl   = blockIdx.y * 8 + w;
    const int fs   = Fp >> 2;

    const float4* pc4 = (const float4*)(pc + (size_t)bl * Fp);
    const float4* pm4 = (const float4*)(pm + (size_t)bl * Fp);
    const float4* pr4 = (const float4*)(pr + (size_t)bl * Fp);
    const float4* wq  = (const float4*)sw;

    ull A[12];
#pragma unroll
    for (int i = 0; i < 12; i++) A[i] = 0;

    int q = lane;
    // unrolled-by-2 main loop: both chunks' loads issue before either body
    for (; q + 32 < fs; q += 64) {
        const float4 ca = pc4[q],      ma = pm4[q],      ra = pr4[q];
        const float4 cb = pc4[q + 32], mb = pm4[q + 32], rb = pr4[q + 32];
        BODY(q, ca, ma, ra);
        BODY(q + 32, cb, mb, rb);
    }
    if (q < fs) {
        const float4 ca = pc4[q], ma = pm4[q], ra = pr4[q];
        BODY(q, ca, ma, ra);
    }

    float r[12];
#pragma unroll
    for (int i = 0; i < 12; i++) {
        float x0, x1; upk2(A[i], x0, x1); r[i] = x0 + x1;
    }
#pragma unroll
    for (int off = 16; off; off >>= 1)
#pragma unroll
        for (int i = 0; i < 12; i++)
            r[i] += __shfl_xor_sync(0xffffffffu, r[i], off);

    if (lane < 4) {
        const int b = bl / L, l = bl - (bl / L) * L;
        const int o = blockIdx.x * 4 + lane;
        const size_t ob = ((size_t)b * O + o) * L + l;
        const float oc = root8(r[3 * lane]);
        const float ol = root8(r[3 * lane + 1]);
        const float oh = root8(r[3 * lane + 2]);
        o0[ob] = oc;
        if (outmode == 0) { o1[ob] = ol; o2[ob] = oh; }
        else              { o1[ob] = 0.5f * (ol + oh); o2[ob] = 0.5f * (oh - ol); }
    }
}

// ---------------------------------------------------------------------------
// Interval-bound linear on (c, m, r) streams, 4 batches per warp.
// mode 0: relu epilogue, outputs (c, m, r); mode 1: final (-c, -u, -l).
// ---------------------------------------------------------------------------
__global__ void __launch_bounds__(256) bound_linear4_kernel(
    const float* __restrict__ inc, const float* __restrict__ inm, const float* __restrict__ inr,
    const float* __restrict__ Wm, const float* __restrict__ bias,
    float* __restrict__ o0, float* __restrict__ o1, float* __restrict__ o2,
    int B, int IN, int OUT, int mode)
{
    const int warp = (blockIdx.x * blockDim.x + threadIdx.x) >> 5;
    const int lane = threadIdx.x & 31;
    const int BG = B >> 2;
    if (warp >= OUT * BG) return;
    const int o  = warp % OUT;
    const int bg = warp / OUT;
    const int b0 = bg * 4;

    const float4* w4 = (const float4*)(Wm + (size_t)o * IN);
    const float4* c4 = (const float4*)(inc + (size_t)b0 * IN);
    const float4* m4 = (const float4*)(inm + (size_t)b0 * IN);
    const float4* r4 = (const float4*)(inr + (size_t)b0 * IN);
    const int n4 = IN >> 2;

    float r[12];
#pragma unroll
    for (int i = 0; i < 12; i++) r[i] = 0.f;

    for (int k = lane; k < n4; k += 32) {
        const float4 wv = w4[k];
        const float awx = fabsf(wv.x), awy = fabsf(wv.y), awz = fabsf(wv.z), aww = fabsf(wv.w);
#pragma unroll
        for (int j = 0; j < 4; j++) {
            const float4 cv = c4[k + (size_t)j * n4];
            const float4 mv = m4[k + (size_t)j * n4];
            const float4 rv = r4[k + (size_t)j * n4];
            float sc = r[j * 3], sm = r[j * 3 + 1], sr = r[j * 3 + 2];
            sc = fmaf(cv.x, wv.x, sc); sc = fmaf(cv.y, wv.y, sc);
            sc = fmaf(cv.z, wv.z, sc); sc = fmaf(cv.w, wv.w, sc);
            sm = fmaf(mv.x, wv.x, sm); sm = fmaf(mv.y, wv.y, sm);
            sm = fmaf(mv.z, wv.z, sm); sm = fmaf(mv.w, wv.w, sm);
            sr = fmaf(rv.x, awx, sr); sr = fmaf(rv.y, awy, sr);
            sr = fmaf(rv.z, awz, sr); sr = fmaf(rv.w, aww, sr);
            r[j * 3] = sc; r[j * 3 + 1] = sm; r[j * 3 + 2] = sr;
        }
    }
#pragma unroll
    for (int off = 16; off; off >>= 1)
#pragma unroll
        for (int i = 0; i < 12; i++)
            r[i] += __shfl_xor_sync(0xffffffffu, r[i], off);

    if (lane < 4) {
        const int b = b0 + lane;
        const float sc = r[lane * 3], sm = r[lane * 3 + 1], sr = r[lane * 3 + 2];
        const size_t idx = (size_t)b * OUT + o;
        if (mode == 0) {
            const float lr = fmaxf(sm - sr, 0.f);
            const float hr = fmaxf(sm + sr, 0.f);
            o0[idx] = fmaxf(sc, 0.f);
            o1[idx] = 0.5f * (lr + hr);
            o2[idx] = 0.5f * (hr - lr);
        } else {
            const float bv  = bias[o];
            const float oc  = sc + bv;
            const float mid = sm + bv;
            o0[idx] = -oc;            // -center
            o1[idx] = -(mid + sr);    // -upper
            o2[idx] = -(mid - sr);    // -lower
        }
    }
}

// ---------------------------------------------------------------------------
// Host orchestration (graph-capturable: launches only).
// ---------------------------------------------------------------------------
static inline int cdiv(int a, int b) { return (a + b - 1) / b; }

extern "C" void kernel_launch(void* const* d_in, const int* in_sizes, int n_in,
                              void* d_out, int out_size)
{
    const float* x   = (const float*)d_in[0];
    const float* lo  = (const float*)d_in[1];
    const float* hi  = (const float*)d_in[2];
    const float* w1  = (const float*)d_in[3];
    const float* w2  = (const float*)d_in[4];
    const float* w3  = (const float*)d_in[5];
    const float* w4  = (const float*)d_in[6];
    const float* w5  = (const float*)d_in[7];
    const float* fw1 = (const float*)d_in[8];
    const float* fw2 = (const float*)d_in[9];
    const float* fw3 = (const float*)d_in[10];
    const float* fb3 = (const float*)d_in[11];
    float* out = (float*)d_out;

    cudaFuncSetAttribute(normdist_conv_s_kernel,
                         cudaFuncAttributeMaxDynamicSharedMemorySize, 56 * 1024);

    float *A, *Bf, *P, *WP;
    cudaGetSymbolAddress((void**)&A,  g_bufA);
    cudaGetSymbolAddress((void**)&Bf, g_bufB);
    cudaGetSymbolAddress((void**)&P,  g_patch);
    cudaGetSymbolAddress((void**)&WP, g_wpad);
    float *A0 = A,  *A1 = A  + VS, *A2 = A  + 2 * VS;
    float *B0 = Bf, *B1 = Bf + VS, *B2 = Bf + 2 * VS;
    float *P0 = P,  *P1 = P  + PS, *P2 = P  + 2 * PS;

#define CONVS(W_, o0, o1, o2, BL_, O_, FP_, L_, MODE_)                              \
    normdist_conv_s_kernel<<<dim3((O_) / 4, (BL_) / 8), 256, 4 * (FP_) * 4>>>(      \
        P0, P1, P2, W_, o0, o1, o2, FP_, L_, O_, MODE_)

    // (1) prep: conv1 patches (c,m,r) from real lower/upper + weight pad
    prep1_kernel<<<cdiv(P1_IM2COL + P1_WPAD, 256), 256>>>(
        x, lo, hi, w1, P0, P1, P2, WP);

    // (2) conv1: -> [16,96,15,15] as (c,ol,oh)
    CONVS(WP, A0, A1, A2, 3600, 96, 148, 225, 0);

    // (3) pool1: -> compact (c,m,r) [16,96,7,7]
    pool3s_kernel<<<cdiv(16 * 96 * 49, 256), 256>>>(
        A0, A1, A2, B0, B1, B2, 16 * 96, 15, 15, 7, 7);

    // (4) gather k=5,p=2: Fp=2400
    gather_kernel<<<cdiv(16 * 49 * 2400, 256), 256>>>(
        B0, B1, B2, P0, P1, P2, 16, 96, 7, 7, 5, 2);

    // (5) conv2: -> [16,256,7,7] as (c,ol,oh)
    CONVS(w2, A0, A1, A2, 784, 256, 2400, 49, 0);

    // (6) pool2: -> compact (c,m,r) [16,256,3,3]
    pool3s_kernel<<<cdiv(16 * 256 * 9, 256), 256>>>(
        A0, A1, A2, B0, B1, B2, 16 * 256, 7, 7, 3, 3);

    // (7) gather k=3,p=1: Fp=2304
    gather_kernel<<<cdiv(16 * 9 * 2304, 256), 256>>>(
        B0, B1, B2, P0, P1, P2, 16, 256, 3, 3, 3, 1);

    // (8) conv3: -> [16,384,3,3] as (c,m,r)
    CONVS(w3, A0, A1, A2, 144, 384, 2304, 9, 1);

    // (9) gather k=3,p=1: Fp=3456
    gather_kernel<<<cdiv(16 * 9 * 3456, 256), 256>>>(
        A0, A1, A2, P0, P1, P2, 16, 384, 3, 3, 3, 1);

    // (10) conv4: -> [16,384,3,3] as (c,m,r)
    CONVS(w4, B0, B1, B2, 144, 384, 3456, 9, 1);

    // (11) gather: Fp=3456
    gather_kernel<<<cdiv(16 * 9 * 3456, 256), 256>>>(
        B0, B1, B2, P0, P1, P2, 16, 384, 3, 3, 3, 1);

    // (12) conv5: -> [16,256,3,3] as (c,m,r) == flattened [16,2304]
    CONVS(w5, A0, A1, A2, 144, 256, 3456, 9, 1);

    // (13) fc1: 2304 -> 1024 (+relu), (c,m,r)
    bound_linear4_kernel<<<cdiv(1024 * 4 * 32, 256), 256>>>(
        A0, A1, A2, fw1, (const float*)nullptr, B0, B1, B2, 16, 2304, 1024, 0);
    // (14) fc2: 1024 -> 512 (+relu)
    bound_linear4_kernel<<<cdiv(512 * 4 * 32, 256), 256>>>(
        B0, B1, B2, fw2, (const float*)nullptr, A0, A1, A2, 16, 1024, 512, 0);
    // (15) fc3: 512 -> 10 (+bias): d_out = [-c | -u | -l]
    bound_linear4_kernel<<<cdiv(10 * 4 * 32, 256), 256>>>(
        A0, A1, A2, fw3, fb3, out, out + 160, out + 320, 16, 512, 10, 1);

#undef CONVS
}

// round 13
// speedup vs baseline: 1.0851x; 1.0108x over previous
#include <cuda_runtime.h>
#include <math.h>

typedef unsigned long long ull;

// ---------------------------------------------------------------------------
// Scratch (device globals; allocations forbidden).
// ---------------------------------------------------------------------------
#define VS 345600
#define PS 1881600
__device__ float g_bufA[3 * VS];
__device__ float g_bufB[3 * VS];
__device__ float g_patch[3 * PS];   // streams: center | mid | rad
__device__ float g_wpad[96 * 148];

#define ABSM 0x7FFFFFFF7FFFFFFFULL
#define M1   0xBF800000BF800000ULL

// ---------------------------------------------------------------------------
// f32x2 packed helpers (sm_103a)
// ---------------------------------------------------------------------------
__device__ __forceinline__ ull pk2(float lo, float hi) {
    ull r; asm("mov.b64 %0, {%1,%2};" : "=l"(r) : "f"(lo), "f"(hi)); return r;
}
__device__ __forceinline__ void upk2(ull v, float& lo, float& hi) {
    asm("mov.b64 {%0,%1}, %2;" : "=f"(lo), "=f"(hi) : "l"(v));
}
__device__ __forceinline__ ull fma2(ull a, ull b, ull c) {
    ull r; asm("fma.rn.f32x2 %0, %1, %2, %3;" : "=l"(r) : "l"(a), "l"(b), "l"(c)); return r;
}
__device__ __forceinline__ ull mul2(ull a, ull b) {
    ull r; asm("mul.rn.f32x2 %0, %1, %2;" : "=l"(r) : "l"(a), "l"(b)); return r;
}
__device__ __forceinline__ ull add2(ull a, ull b) {
    ull r; asm("add.rn.f32x2 %0, %1, %2;" : "=l"(r) : "l"(a), "l"(b)); return r;
}
__device__ __forceinline__ float root8(float s) { return sqrtf(sqrtf(sqrtf(s))); }

// All-packed bound-distance accumulation (13 fma-pipe ops / HALF).
// a = mid - w;  dh = |a|+rad;  dl = relu(|a|-rad) via scalar FMNMX (alu pipe);
// dc = vc - w.
#define HALF(W, VC, MD, RD, AC, AL, AH) {                               \
        ull dc = fma2(W, M1, VC);                                       \
        ull s  = mul2(dc, dc); s = mul2(s, s); AC = fma2(s, s, AC);     \
        ull a  = fma2(W, M1, MD);                                       \
        ull aa = a & ABSM;                                              \
        ull dh = add2(aa, RD);                                          \
        s = mul2(dh, dh); s = mul2(s, s); AH = fma2(s, s, AH);          \
        ull t  = fma2(RD, M1, aa);                                      \
        float t0, t1; upk2(t, t0, t1);                                  \
        ull v  = pk2(fmaxf(t0, 0.f), fmaxf(t1, 0.f));                   \
        s = mul2(v, v); s = mul2(s, s); AL = fma2(s, s, AL); }

// One 4-channel x 4-f-element compute body (weights from smem).
#define BODY(Q, C4, M4, R4) {                                           \
        const ull c01 = pk2(C4.x, C4.y), c23 = pk2(C4.z, C4.w);         \
        const ull m01 = pk2(M4.x, M4.y), m23 = pk2(M4.z, M4.w);         \
        const ull r01 = pk2(R4.x, R4.y), r23 = pk2(R4.z, R4.w);         \
        _Pragma("unroll")                                               \
        for (int ch = 0; ch < 4; ch++) {                                \
            const float4 wv = wq[(Q) + ch * fs];                        \
            const ull w01 = pk2(wv.x, wv.y), w23 = pk2(wv.z, wv.w);     \
            HALF(w01, c01, m01, r01, A[ch*3], A[ch*3+1], A[ch*3+2]);    \
            HALF(w23, c23, m23, r23, A[ch*3], A[ch*3+1], A[ch*3+2]);    \
        } }

// ---------------------------------------------------------------------------
// prep1: conv1 im2col of (center, mid, rad) from real lower/upper inputs
// (Fp 147->148 zero-pad) + conv1 weight pad.
// ---------------------------------------------------------------------------
#define P1_IM2COL (16 * 225 * 148)
#define P1_WPAD   (96 * 148)
__global__ void __launch_bounds__(256) prep1_kernel(
    const float* __restrict__ ic, const float* __restrict__ il, const float* __restrict__ ih,
    const float* __restrict__ w1,
    float* __restrict__ oc, float* __restrict__ om, float* __restrict__ orr,
    float* __restrict__ wp)
{
    const int idx = blockIdx.x * blockDim.x + threadIdx.x;
    if (idx < P1_IM2COL) {
        const int f  = idx % 148;
        const int bl = idx / 148;
        const int l  = bl % 225;
        const int b  = bl / 225;
        float vc = 0.f, vm = 0.f, vr = 0.f;
        if (f < 147) {
            const int c  = f / 49;
            const int r  = f - c * 49;
            const int ky = r / 7, kx = r - (r / 7) * 7;
            const int oy = l / 15, ox = l - (l / 15) * 15;
            const int iy = oy * 2 - 2 + ky;
            const int ix = ox * 2 - 2 + kx;
            if ((unsigned)iy < 32u && (unsigned)ix < 32u) {
                const int si = ((b * 3 + c) * 32 + iy) * 32 + ix;
                const float lv = il[si], hv = ih[si];
                vc = ic[si]; vm = 0.5f * (lv + hv); vr = 0.5f * (hv - lv);
            }
        }
        oc[idx] = vc; om[idx] = vm; orr[idx] = vr;
    } else if (idx < P1_IM2COL + P1_WPAD) {
        const int j = idx - P1_IM2COL;
        const int f = j % 148, o = j / 148;
        wp[j] = (f < 147) ? w1[o * 147 + f] : 0.f;
    }
}

// ---------------------------------------------------------------------------
// 3x3/s2 maxpool on RAW 8th-power sums (sc, sl, sh) -> root8 on the pooled
// maxima (exact: root8 is monotone, commutes with max) -> (c, mid, rad).
// ---------------------------------------------------------------------------
__global__ void __launch_bounds__(256) pool3s_kernel(
    const float* __restrict__ ic, const float* __restrict__ il, const float* __restrict__ ih,
    float* __restrict__ oc, float* __restrict__ om, float* __restrict__ orr,
    int NC, int H, int W, int h, int w)
{
    const int i = blockIdx.x * blockDim.x + threadIdx.x;
    if (i >= NC * h * w) return;
    const int x = i % w;
    const int y = (i / w) % h;
    const int n = i / (w * h);
    const int base = (n * H + y * 2) * W + x * 2;
    float m0 = 0.f, m1 = 0.f, m2 = 0.f;   // sums are >= 0
#pragma unroll
    for (int ky = 0; ky < 3; ky++)
#pragma unroll
        for (int kx = 0; kx < 3; kx++) {
            const int si = base + ky * W + kx;
            m0 = fmaxf(m0, ic[si]);
            m1 = fmaxf(m1, il[si]);
            m2 = fmaxf(m2, ih[si]);
        }
    const float cv = root8(m0);
    const float lv = root8(m1);
    const float hv = root8(m2);
    oc[i] = cv; om[i] = 0.5f * (lv + hv); orr[i] = 0.5f * (hv - lv);
}

// ---------------------------------------------------------------------------
// Pure gather im2col, fully templated (constant div/mod -> mul-shift).
// compact (c,m,r) [16,C,HW,HW] -> patch streams.
// ---------------------------------------------------------------------------
template<int C, int HW, int K, int PAD>
__global__ void __launch_bounds__(256) gather_t_kernel(
    const float* __restrict__ ic, const float* __restrict__ im, const float* __restrict__ ir,
    float* __restrict__ oc, float* __restrict__ om, float* __restrict__ orr)
{
    constexpr int Fp = C * K * K;
    constexpr int L  = HW * HW;
    constexpr int N  = 16 * L * Fp;
    const int idx = blockIdx.x * blockDim.x + threadIdx.x;
    if (idx >= N) return;
    const int f  = idx % Fp;
    const int bl = idx / Fp;
    const int l  = bl % L;
    const int b  = bl / L;
    const int c  = f / (K * K);
    const int r  = f % (K * K);
    const int ky = r / K, kx = r % K;
    const int oy = l / HW, ox = l % HW;
    const int py = oy - PAD + ky;
    const int px = ox - PAD + kx;
    float vc = 0.f, vm = 0.f, vr = 0.f;
    if ((unsigned)py < (unsigned)HW && (unsigned)px < (unsigned)HW) {
        const int si = ((b * C + c) * HW + py) * HW + px;
        vc = ic[si]; vm = im[si]; vr = ir[si];
    }
    oc[idx] = vc; om[idx] = vm; orr[idx] = vr;
}

// ---------------------------------------------------------------------------
// Packed NormDist (L8) conv: block = 8 warps, 1 og-quad of weights in smem,
// 8 bl per block. grid = (O/4, BL/8).
// fs > 64: unroll-2 with batched loads (MLP=6); fs <= 64: plain loop
// (avoids the divergent 3-BODY pattern conv1 hit with unroll-2 at fs=37).
// outmode 0: write RAW sums (sc, sl, sh) -- consumer pool does root8.
// outmode 1: write (c, mid, rad) with root8 in epilogue.
// ---------------------------------------------------------------------------
__global__ void __launch_bounds__(256, 3) normdist_conv_s_kernel(
    const float* __restrict__ pc, const float* __restrict__ pm, const float* __restrict__ pr,
    const float* __restrict__ wgt,
    float* __restrict__ o0, float* __restrict__ o1, float* __restrict__ o2,
    int Fp, int L, int O, int outmode)
{
    extern __shared__ float sw[];
    const int tid = threadIdx.x;
    {
        const float4* src = (const float4*)(wgt + (size_t)blockIdx.x * 4 * Fp);
        float4* dst = (float4*)sw;
        for (int i = tid; i < Fp; i += 256) dst[i] = src[i];
    }
    __syncthreads();

    const int w    = tid >> 5;
    const int lane = tid & 31;
    const int bl   = blockIdx.y * 8 + w;
    const int fs   = Fp >> 2;

    const float4* pc4 = (const float4*)(pc + (size_t)bl * Fp);
    const float4* pm4 = (const float4*)(pm + (size_t)bl * Fp);
    const float4* pr4 = (const float4*)(pr + (size_t)bl * Fp);
    const float4* wq  = (const float4*)sw;

    ull A[12];
#pragma unroll
    for (int i = 0; i < 12; i++) A[i] = 0;

    if (fs > 64) {
        int q = lane;
        for (; q + 32 < fs; q += 64) {
            const float4 ca = pc4[q],      ma = pm4[q],      ra = pr4[q];
            const float4 cb = pc4[q + 32], mb = pm4[q + 32], rb = pr4[q + 32];
            BODY(q, ca, ma, ra);
            BODY(q + 32, cb, mb, rb);
        }
        if (q < fs) {
            const float4 ca = pc4[q], ma = pm4[q], ra = pr4[q];
            BODY(q, ca, ma, ra);
        }
    } else {
        for (int q = lane; q < fs; q += 32) {
            const float4 ca = pc4[q], ma = pm4[q], ra = pr4[q];
            BODY(q, ca, ma, ra);
        }
    }

    float r[12];
#pragma unroll
    for (int i = 0; i < 12; i++) {
        float x0, x1; upk2(A[i], x0, x1); r[i] = x0 + x1;
    }
#pragma unroll
    for (int off = 16; off; off >>= 1)
#pragma unroll
        for (int i = 0; i < 12; i++)
            r[i] += __shfl_xor_sync(0xffffffffu, r[i], off);

    if (lane < 4) {
        const int b = bl / L, l = bl - (bl / L) * L;
        const int o = blockIdx.x * 4 + lane;
        const size_t ob = ((size_t)b * O + o) * L + l;
        if (outmode == 0) {
            // raw 8th-power sums; pool applies root8 after max
            o0[ob] = r[3 * lane];
            o1[ob] = r[3 * lane + 1];
            o2[ob] = r[3 * lane + 2];
        } else {
            const float oc = root8(r[3 * lane]);
            const float ol = root8(r[3 * lane + 1]);
            const float oh = root8(r[3 * lane + 2]);
            o0[ob] = oc;
            o1[ob] = 0.5f * (ol + oh);
            o2[ob] = 0.5f * (oh - ol);
        }
    }
}

// ---------------------------------------------------------------------------
// Interval-bound linear on (c, m, r) streams, 4 batches per warp.
// mode 0: relu epilogue, outputs (c, m, r); mode 1: final (-c, -u, -l).
// ---------------------------------------------------------------------------
__global__ void __launch_bounds__(256) bound_linear4_kernel(
    const float* __restrict__ inc, const float* __restrict__ inm, const float* __restrict__ inr,
    const float* __restrict__ Wm, const float* __restrict__ bias,
    float* __restrict__ o0, float* __restrict__ o1, float* __restrict__ o2,
    int B, int IN, int OUT, int mode)
{
    const int warp = (blockIdx.x * blockDim.x + threadIdx.x) >> 5;
    const int lane = threadIdx.x & 31;
    const int BG = B >> 2;
    if (warp >= OUT * BG) return;
    const int o  = warp % OUT;
    const int bg = warp / OUT;
    const int b0 = bg * 4;

    const float4* w4 = (const float4*)(Wm + (size_t)o * IN);
    const float4* c4 = (const float4*)(inc + (size_t)b0 * IN);
    const float4* m4 = (const float4*)(inm + (size_t)b0 * IN);
    const float4* r4 = (const float4*)(inr + (size_t)b0 * IN);
    const int n4 = IN >> 2;

    float r[12];
#pragma unroll
    for (int i = 0; i < 12; i++) r[i] = 0.f;

    for (int k = lane; k < n4; k += 32) {
        const float4 wv = w4[k];
        const float awx = fabsf(wv.x), awy = fabsf(wv.y), awz = fabsf(wv.z), aww = fabsf(wv.w);
#pragma unroll
        for (int j = 0; j < 4; j++) {
            const float4 cv = c4[k + (size_t)j * n4];
            const float4 mv = m4[k + (size_t)j * n4];
            const float4 rv = r4[k + (size_t)j * n4];
            float sc = r[j * 3], sm = r[j * 3 + 1], sr = r[j * 3 + 2];
            sc = fmaf(cv.x, wv.x, sc); sc = fmaf(cv.y, wv.y, sc);
            sc = fmaf(cv.z, wv.z, sc); sc = fmaf(cv.w, wv.w, sc);
            sm = fmaf(mv.x, wv.x, sm); sm = fmaf(mv.y, wv.y, sm);
            sm = fmaf(mv.z, wv.z, sm); sm = fmaf(mv.w, wv.w, sm);
            sr = fmaf(rv.x, awx, sr); sr = fmaf(rv.y, awy, sr);
            sr = fmaf(rv.z, awz, sr); sr = fmaf(rv.w, aww, sr);
            r[j * 3] = sc; r[j * 3 + 1] = sm; r[j * 3 + 2] = sr;
        }
    }
#pragma unroll
    for (int off = 16; off; off >>= 1)
#pragma unroll
        for (int i = 0; i < 12; i++)
            r[i] += __shfl_xor_sync(0xffffffffu, r[i], off);

    if (lane < 4) {
        const int b = b0 + lane;
        const float sc = r[lane * 3], sm = r[lane * 3 + 1], sr = r[lane * 3 + 2];
        const size_t idx = (size_t)b * OUT + o;
        if (mode == 0) {
            const float lr = fmaxf(sm - sr, 0.f);
            const float hr = fmaxf(sm + sr, 0.f);
            o0[idx] = fmaxf(sc, 0.f);
            o1[idx] = 0.5f * (lr + hr);
            o2[idx] = 0.5f * (hr - lr);
        } else {
            const float bv  = bias[o];
            const float oc  = sc + bv;
            const float mid = sm + bv;
            o0[idx] = -oc;            // -center
            o1[idx] = -(mid + sr);    // -upper
            o2[idx] = -(mid - sr);    // -lower
        }
    }
}

// ---------------------------------------------------------------------------
// Host orchestration (graph-capturable: launches only).
// ---------------------------------------------------------------------------
static inline int cdiv(int a, int b) { return (a + b - 1) / b; }

extern "C" void kernel_launch(void* const* d_in, const int* in_sizes, int n_in,
                              void* d_out, int out_size)
{
    const float* x   = (const float*)d_in[0];
    const float* lo  = (const float*)d_in[1];
    const float* hi  = (const float*)d_in[2];
    const float* w1  = (const float*)d_in[3];
    const float* w2  = (const float*)d_in[4];
    const float* w3  = (const float*)d_in[5];
    const float* w4  = (const float*)d_in[6];
    const float* w5  = (const float*)d_in[7];
    const float* fw1 = (const float*)d_in[8];
    const float* fw2 = (const float*)d_in[9];
    const float* fw3 = (const float*)d_in[10];
    const float* fb3 = (const float*)d_in[11];
    float* out = (float*)d_out;

    cudaFuncSetAttribute(normdist_conv_s_kernel,
                         cudaFuncAttributeMaxDynamicSharedMemorySize, 56 * 1024);

    float *A, *Bf, *P, *WP;
    cudaGetSymbolAddress((void**)&A,  g_bufA);
    cudaGetSymbolAddress((void**)&Bf, g_bufB);
    cudaGetSymbolAddress((void**)&P,  g_patch);
    cudaGetSymbolAddress((void**)&WP, g_wpad);
    float *A0 = A,  *A1 = A  + VS, *A2 = A  + 2 * VS;
    float *B0 = Bf, *B1 = Bf + VS, *B2 = Bf + 2 * VS;
    float *P0 = P,  *P1 = P  + PS, *P2 = P  + 2 * PS;

#define CONVS(W_, o0, o1, o2, BL_, O_, FP_, L_, MODE_)                              \
    normdist_conv_s_kernel<<<dim3((O_) / 4, (BL_) / 8), 256, 4 * (FP_) * 4>>>(      \
        P0, P1, P2, W_, o0, o1, o2, FP_, L_, O_, MODE_)

    // (1) prep: conv1 patches (c,m,r) from real lower/upper + weight pad
    prep1_kernel<<<cdiv(P1_IM2COL + P1_WPAD, 256), 256>>>(
        x, lo, hi, w1, P0, P1, P2, WP);

    // (2) conv1: -> [16,96,15,15] RAW sums
    CONVS(WP, A0, A1, A2, 3600, 96, 148, 225, 0);

    // (3) pool1 (max on raw sums, then root8): -> compact (c,m,r) [16,96,7,7]
    pool3s_kernel<<<cdiv(16 * 96 * 49, 256), 256>>>(
        A0, A1, A2, B0, B1, B2, 16 * 96, 15, 15, 7, 7);

    // (4) gather k=5,p=2: Fp=2400
    gather_t_kernel<96, 7, 5, 2><<<cdiv(16 * 49 * 2400, 256), 256>>>(
        B0, B1, B2, P0, P1, P2);

    // (5) conv2: -> [16,256,7,7] RAW sums
    CONVS(w2, A0, A1, A2, 784, 256, 2400, 49, 0);

    // (6) pool2: -> compact (c,m,r) [16,256,3,3]
    pool3s_kernel<<<cdiv(16 * 256 * 9, 256), 256>>>(
        A0, A1, A2, B0, B1, B2, 16 * 256, 7, 7, 3, 3);

    // (7) gather k=3,p=1: Fp=2304
    gather_t_kernel<256, 3, 3, 1><<<cdiv(16 * 9 * 2304, 256), 256>>>(
        B0, B1, B2, P0, P1, P2);

    // (8) conv3: -> [16,384,3,3] as (c,m,r)
    CONVS(w3, A0, A1, A2, 144, 384, 2304, 9, 1);

    // (9) gather k=3,p=1: Fp=3456
    gather_t_kernel<384, 3, 3, 1><<<cdiv(16 * 9 * 3456, 256), 256>>>(
        A0, A1, A2, P0, P1, P2);

    // (10) conv4: -> [16,384,3,3] as (c,m,r)
    CONVS(w4, B0, B1, B2, 144, 384, 3456, 9, 1);

    // (11) gather: Fp=3456
    gather_t_kernel<384, 3, 3, 1><<<cdiv(16 * 9 * 3456, 256), 256>>>(
        B0, B1, B2, P0, P1, P2);

    // (12) conv5: -> [16,256,3,3] as (c,m,r) == flattened [16,2304]
    CONVS(w5, A0, A1, A2, 144, 256, 3456, 9, 1);

    // (13) fc1: 2304 -> 1024 (+relu), (c,m,r)
    bound_linear4_kernel<<<cdiv(1024 * 4 * 32, 256), 256>>>(
        A0, A1, A2, fw1, (const float*)nullptr, B0, B1, B2, 16, 2304, 1024, 0);
    // (14) fc2: 1024 -> 512 (+relu)
    bound_linear4_kernel<<<cdiv(512 * 4 * 32, 256), 256>>>(
        B0, B1, B2, fw2, (const float*)nullptr, A0, A1, A2, 16, 1024, 512, 0);
    // (15) fc3: 512 -> 10 (+bias): d_out = [-c | -u | -l]
    bound_linear4_kernel<<<cdiv(10 * 4 * 32, 256), 256>>>(
        A0, A1, A2, fw3, fb3, out, out + 160, out + 320, 16, 512, 10, 1);

#undef CONVS
}

// round 14
// speedup vs baseline: 1.1852x; 1.0922x over previous
#include <cuda_runtime.h>
#include <math.h>

typedef unsigned long long ull;

// ---------------------------------------------------------------------------
// Scratch (device globals; allocations forbidden).
// ---------------------------------------------------------------------------
#define VS 345600
#define PS 1881600
__device__ float g_bufA[3 * VS];
__device__ float g_bufB[3 * VS];
__device__ float g_patch[3 * PS];   // streams: center | mid | rad
__device__ float g_wpad[96 * 148];

#define ABSM 0x7FFFFFFF7FFFFFFFULL
#define M1   0xBF800000BF800000ULL

// ---------------------------------------------------------------------------
// f32x2 packed helpers (sm_103a)
// ---------------------------------------------------------------------------
__device__ __forceinline__ ull pk2(float lo, float hi) {
    ull r; asm("mov.b64 %0, {%1,%2};" : "=l"(r) : "f"(lo), "f"(hi)); return r;
}
__device__ __forceinline__ void upk2(ull v, float& lo, float& hi) {
    asm("mov.b64 {%0,%1}, %2;" : "=f"(lo), "=f"(hi) : "l"(v));
}
__device__ __forceinline__ ull fma2(ull a, ull b, ull c) {
    ull r; asm("fma.rn.f32x2 %0, %1, %2, %3;" : "=l"(r) : "l"(a), "l"(b), "l"(c)); return r;
}
__device__ __forceinline__ ull mul2(ull a, ull b) {
    ull r; asm("mul.rn.f32x2 %0, %1, %2;" : "=l"(r) : "l"(a), "l"(b)); return r;
}
__device__ __forceinline__ ull add2(ull a, ull b) {
    ull r; asm("add.rn.f32x2 %0, %1, %2;" : "=l"(r) : "l"(a), "l"(b)); return r;
}
__device__ __forceinline__ float root8(float s) { return sqrtf(sqrtf(sqrtf(s))); }

// All-packed bound-distance accumulation (13 fma-pipe ops / HALF).
// a = mid - w;  dh = |a|+rad;  dl = relu(|a|-rad) via scalar FMNMX (alu pipe);
// dc = vc - w.
#define HALF(W, VC, MD, RD, AC, AL, AH) {                               \
        ull dc = fma2(W, M1, VC);                                       \
        ull s  = mul2(dc, dc); s = mul2(s, s); AC = fma2(s, s, AC);     \
        ull a  = fma2(W, M1, MD);                                       \
        ull aa = a & ABSM;                                              \
        ull dh = add2(aa, RD);                                          \
        s = mul2(dh, dh); s = mul2(s, s); AH = fma2(s, s, AH);          \
        ull t  = fma2(RD, M1, aa);                                      \
        float t0, t1; upk2(t, t0, t1);                                  \
        ull v  = pk2(fmaxf(t0, 0.f), fmaxf(t1, 0.f));                   \
        s = mul2(v, v); s = mul2(s, s); AL = fma2(s, s, AL); }

// One 4-channel x 4-f-element compute body (weights from smem, fs const).
#define BODY(Q, C4, M4, R4) {                                           \
        const ull c01 = pk2(C4.x, C4.y), c23 = pk2(C4.z, C4.w);         \
        const ull m01 = pk2(M4.x, M4.y), m23 = pk2(M4.z, M4.w);         \
        const ull r01 = pk2(R4.x, R4.y), r23 = pk2(R4.z, R4.w);         \
        _Pragma("unroll")                                               \
        for (int ch = 0; ch < 4; ch++) {                                \
            const float4 wv = wq[(Q) + ch * fs];                        \
            const ull w01 = pk2(wv.x, wv.y), w23 = pk2(wv.z, wv.w);     \
            HALF(w01, c01, m01, r01, A[ch*3], A[ch*3+1], A[ch*3+2]);    \
            HALF(w23, c23, m23, r23, A[ch*3], A[ch*3+1], A[ch*3+2]);    \
        } }

// ---------------------------------------------------------------------------
// prep1: conv1 im2col of (center, mid, rad) from real lower/upper inputs
// (Fp 147->148 zero-pad) + conv1 weight pad.
// ---------------------------------------------------------------------------
#define P1_IM2COL (16 * 225 * 148)
#define P1_WPAD   (96 * 148)
__global__ void __launch_bounds__(256) prep1_kernel(
    const float* __restrict__ ic, const float* __restrict__ il, const float* __restrict__ ih,
    const float* __restrict__ w1,
    float* __restrict__ oc, float* __restrict__ om, float* __restrict__ orr,
    float* __restrict__ wp)
{
    const int idx = blockIdx.x * blockDim.x + threadIdx.x;
    if (idx < P1_IM2COL) {
        const int f  = idx % 148;
        const int bl = idx / 148;
        const int l  = bl % 225;
        const int b  = bl / 225;
        float vc = 0.f, vm = 0.f, vr = 0.f;
        if (f < 147) {
            const int c  = f / 49;
            const int r  = f - c * 49;
            const int ky = r / 7, kx = r - (r / 7) * 7;
            const int oy = l / 15, ox = l - (l / 15) * 15;
            const int iy = oy * 2 - 2 + ky;
            const int ix = ox * 2 - 2 + kx;
            if ((unsigned)iy < 32u && (unsigned)ix < 32u) {
                const int si = ((b * 3 + c) * 32 + iy) * 32 + ix;
                const float lv = il[si], hv = ih[si];
                vc = ic[si]; vm = 0.5f * (lv + hv); vr = 0.5f * (hv - lv);
            }
        }
        oc[idx] = vc; om[idx] = vm; orr[idx] = vr;
    } else if (idx < P1_IM2COL + P1_WPAD) {
        const int j = idx - P1_IM2COL;
        const int f = j % 148, o = j / 148;
        wp[j] = (f < 147) ? w1[o * 147 + f] : 0.f;
    }
}

// ---------------------------------------------------------------------------
// 3x3/s2 maxpool on RAW 8th-power sums -> root8 on pooled maxima (exact)
// -> (c, mid, rad).
// ---------------------------------------------------------------------------
__global__ void __launch_bounds__(256) pool3s_kernel(
    const float* __restrict__ ic, const float* __restrict__ il, const float* __restrict__ ih,
    float* __restrict__ oc, float* __restrict__ om, float* __restrict__ orr,
    int NC, int H, int W, int h, int w)
{
    const int i = blockIdx.x * blockDim.x + threadIdx.x;
    if (i >= NC * h * w) return;
    const int x = i % w;
    const int y = (i / w) % h;
    const int n = i / (w * h);
    const int base = (n * H + y * 2) * W + x * 2;
    float m0 = 0.f, m1 = 0.f, m2 = 0.f;   // sums are >= 0
#pragma unroll
    for (int ky = 0; ky < 3; ky++)
#pragma unroll
        for (int kx = 0; kx < 3; kx++) {
            const int si = base + ky * W + kx;
            m0 = fmaxf(m0, ic[si]);
            m1 = fmaxf(m1, il[si]);
            m2 = fmaxf(m2, ih[si]);
        }
    const float cv = root8(m0);
    const float lv = root8(m1);
    const float hv = root8(m2);
    oc[i] = cv; om[i] = 0.5f * (lv + hv); orr[i] = 0.5f * (hv - lv);
}

// ---------------------------------------------------------------------------
// Pure gather im2col, fully templated.
// ---------------------------------------------------------------------------
template<int C, int HW, int K, int PAD>
__global__ void __launch_bounds__(256) gather_t_kernel(
    const float* __restrict__ ic, const float* __restrict__ im, const float* __restrict__ ir,
    float* __restrict__ oc, float* __restrict__ om, float* __restrict__ orr)
{
    constexpr int Fp = C * K * K;
    constexpr int L  = HW * HW;
    constexpr int N  = 16 * L * Fp;
    const int idx = blockIdx.x * blockDim.x + threadIdx.x;
    if (idx >= N) return;
    const int f  = idx % Fp;
    const int bl = idx / Fp;
    const int l  = bl % L;
    const int b  = bl / L;
    const int c  = f / (K * K);
    const int r  = f % (K * K);
    const int ky = r / K, kx = r % K;
    const int oy = l / HW, ox = l % HW;
    const int py = oy - PAD + ky;
    const int px = ox - PAD + kx;
    float vc = 0.f, vm = 0.f, vr = 0.f;
    if ((unsigned)py < (unsigned)HW && (unsigned)px < (unsigned)HW) {
        const int si = ((b * C + c) * HW + py) * HW + px;
        vc = ic[si]; vm = im[si]; vr = ir[si];
    }
    oc[idx] = vc; om[idx] = vm; orr[idx] = vr;
}

// ---------------------------------------------------------------------------
// Packed NormDist (L8) conv, fully templated <FP, OUTMODE, MINB>.
// Block = 8 warps, 1 og-quad of weights in smem, 8 bl per block.
// grid = (O/4, BL/8). FP/fs compile-time: constant smem indexing, fixed
// trip counts, no epilogue branch.
// OUTMODE 0: write RAW sums; OUTMODE 1: write (c, mid, rad) with root8.
// ---------------------------------------------------------------------------
template<int FP, int OUTMODE, int MINB>
__global__ void __launch_bounds__(256, MINB) normdist_conv_t(
    const float* __restrict__ pc, const float* __restrict__ pm, const float* __restrict__ pr,
    const float* __restrict__ wgt,
    float* __restrict__ o0, float* __restrict__ o1, float* __restrict__ o2,
    int L, int O)
{
    extern __shared__ float swd[];
    constexpr int fs = FP >> 2;
    const int tid = threadIdx.x;
    {
        const float4* src = (const float4*)(wgt + (size_t)blockIdx.x * 4 * FP);
        float4* dst = (float4*)swd;
#pragma unroll
        for (int i = tid; i < FP; i += 256) dst[i] = src[i];
    }
    __syncthreads();

    const int w    = tid >> 5;
    const int lane = tid & 31;
    const int bl   = blockIdx.y * 8 + w;

    const float4* pc4 = (const float4*)(pc + (size_t)bl * FP);
    const float4* pm4 = (const float4*)(pm + (size_t)bl * FP);
    const float4* pr4 = (const float4*)(pr + (size_t)bl * FP);
    const float4* wq  = (const float4*)swd;

    ull A[12];
#pragma unroll
    for (int i = 0; i < 12; i++) A[i] = 0;

    if (fs > 64) {
        int q = lane;
        for (; q + 32 < fs; q += 64) {
            const float4 ca = pc4[q],      ma = pm4[q],      ra = pr4[q];
            const float4 cb = pc4[q + 32], mb = pm4[q + 32], rb = pr4[q + 32];
            BODY(q, ca, ma, ra);
            BODY(q + 32, cb, mb, rb);
        }
        if (q < fs) {
            const float4 ca = pc4[q], ma = pm4[q], ra = pr4[q];
            BODY(q, ca, ma, ra);
        }
    } else {
#pragma unroll
        for (int qq = 0; qq < (fs + 31) / 32; qq++) {
            const int q = qq * 32 + lane;
            if (q < fs) {
                const float4 ca = pc4[q], ma = pm4[q], ra = pr4[q];
                BODY(q, ca, ma, ra);
            }
        }
    }

    float r[12];
#pragma unroll
    for (int i = 0; i < 12; i++) {
        float x0, x1; upk2(A[i], x0, x1); r[i] = x0 + x1;
    }
#pragma unroll
    for (int off = 16; off; off >>= 1)
#pragma unroll
        for (int i = 0; i < 12; i++)
            r[i] += __shfl_xor_sync(0xffffffffu, r[i], off);

    if (lane < 4) {
        const int b = bl / L, l = bl - (bl / L) * L;
        const int o = blockIdx.x * 4 + lane;
        const size_t ob = ((size_t)b * O + o) * L + l;
        if (OUTMODE == 0) {
            o0[ob] = r[3 * lane];
            o1[ob] = r[3 * lane + 1];
            o2[ob] = r[3 * lane + 2];
        } else {
            const float oc = root8(r[3 * lane]);
            const float ol = root8(r[3 * lane + 1]);
            const float oh = root8(r[3 * lane + 2]);
            o0[ob] = oc;
            o1[ob] = 0.5f * (ol + oh);
            o2[ob] = 0.5f * (oh - ol);
        }
    }
}

// ---------------------------------------------------------------------------
// Interval-bound linear on (c, m, r) streams, 4 batches per warp.
// mode 0: relu epilogue, outputs (c, m, r); mode 1: final (-c, -u, -l).
// ---------------------------------------------------------------------------
__global__ void __launch_bounds__(256) bound_linear4_kernel(
    const float* __restrict__ inc, const float* __restrict__ inm, const float* __restrict__ inr,
    const float* __restrict__ Wm, const float* __restrict__ bias,
    float* __restrict__ o0, float* __restrict__ o1, float* __restrict__ o2,
    int B, int IN, int OUT, int mode)
{
    const int warp = (blockIdx.x * blockDim.x + threadIdx.x) >> 5;
    const int lane = threadIdx.x & 31;
    const int BG = B >> 2;
    if (warp >= OUT * BG) return;
    const int o  = warp % OUT;
    const int bg = warp / OUT;
    const int b0 = bg * 4;

    const float4* w4 = (const float4*)(Wm + (size_t)o * IN);
    const float4* c4 = (const float4*)(inc + (size_t)b0 * IN);
    const float4* m4 = (const float4*)(inm + (size_t)b0 * IN);
    const float4* r4 = (const float4*)(inr + (size_t)b0 * IN);
    const int n4 = IN >> 2;

    float r[12];
#pragma unroll
    for (int i = 0; i < 12; i++) r[i] = 0.f;

    for (int k = lane; k < n4; k += 32) {
        const float4 wv = w4[k];
        const float awx = fabsf(wv.x), awy = fabsf(wv.y), awz = fabsf(wv.z), aww = fabsf(wv.w);
#pragma unroll
        for (int j = 0; j < 4; j++) {
            const float4 cv = c4[k + (size_t)j * n4];
            const float4 mv = m4[k + (size_t)j * n4];
            const float4 rv = r4[k + (size_t)j * n4];
            float sc = r[j * 3], sm = r[j * 3 + 1], sr = r[j * 3 + 2];
            sc = fmaf(cv.x, wv.x, sc); sc = fmaf(cv.y, wv.y, sc);
            sc = fmaf(cv.z, wv.z, sc); sc = fmaf(cv.w, wv.w, sc);
            sm = fmaf(mv.x, wv.x, sm); sm = fmaf(mv.y, wv.y, sm);
            sm = fmaf(mv.z, wv.z, sm); sm = fmaf(mv.w, wv.w, sm);
            sr = fmaf(rv.x, awx, sr); sr = fmaf(rv.y, awy, sr);
            sr = fmaf(rv.z, awz, sr); sr = fmaf(rv.w, aww, sr);
            r[j * 3] = sc; r[j * 3 + 1] = sm; r[j * 3 + 2] = sr;
        }
    }
#pragma unroll
    for (int off = 16; off; off >>= 1)
#pragma unroll
        for (int i = 0; i < 12; i++)
            r[i] += __shfl_xor_sync(0xffffffffu, r[i], off);

    if (lane < 4) {
        const int b = b0 + lane;
        const float sc = r[lane * 3], sm = r[lane * 3 + 1], sr = r[lane * 3 + 2];
        const size_t idx = (size_t)b * OUT + o;
        if (mode == 0) {
            const float lr = fmaxf(sm - sr, 0.f);
            const float hr = fmaxf(sm + sr, 0.f);
            o0[idx] = fmaxf(sc, 0.f);
            o1[idx] = 0.5f * (lr + hr);
            o2[idx] = 0.5f * (hr - lr);
        } else {
            const float bv  = bias[o];
            const float oc  = sc + bv;
            const float mid = sm + bv;
            o0[idx] = -oc;            // -center
            o1[idx] = -(mid + sr);    // -upper
            o2[idx] = -(mid - sr);    // -lower
        }
    }
}

// ---------------------------------------------------------------------------
// Host orchestration (graph-capturable: launches only).
// ---------------------------------------------------------------------------
static inline int cdiv(int a, int b) { return (a + b - 1) / b; }

extern "C" void kernel_launch(void* const* d_in, const int* in_sizes, int n_in,
                              void* d_out, int out_size)
{
    const float* x   = (const float*)d_in[0];
    const float* lo  = (const float*)d_in[1];
    const float* hi  = (const float*)d_in[2];
    const float* w1  = (const float*)d_in[3];
    const float* w2  = (const float*)d_in[4];
    const float* w3  = (const float*)d_in[5];
    const float* w4  = (const float*)d_in[6];
    const float* w5  = (const float*)d_in[7];
    const float* fw1 = (const float*)d_in[8];
    const float* fw2 = (const float*)d_in[9];
    const float* fw3 = (const float*)d_in[10];
    const float* fb3 = (const float*)d_in[11];
    float* out = (float*)d_out;

    cudaFuncSetAttribute(normdist_conv_t<2400, 0, 3>,
                         cudaFuncAttributeMaxDynamicSharedMemorySize, 56 * 1024);
    cudaFuncSetAttribute(normdist_conv_t<2304, 1, 3>,
                         cudaFuncAttributeMaxDynamicSharedMemorySize, 56 * 1024);
    cudaFuncSetAttribute(normdist_conv_t<3456, 1, 3>,
                         cudaFuncAttributeMaxDynamicSharedMemorySize, 56 * 1024);

    float *A, *Bf, *P, *WP;
    cudaGetSymbolAddress((void**)&A,  g_bufA);
    cudaGetSymbolAddress((void**)&Bf, g_bufB);
    cudaGetSymbolAddress((void**)&P,  g_patch);
    cudaGetSymbolAddress((void**)&WP, g_wpad);
    float *A0 = A,  *A1 = A  + VS, *A2 = A  + 2 * VS;
    float *B0 = Bf, *B1 = Bf + VS, *B2 = Bf + 2 * VS;
    float *P0 = P,  *P1 = P  + PS, *P2 = P  + 2 * PS;

    // (1) prep: conv1 patches (c,m,r) from real lower/upper + weight pad
    prep1_kernel<<<cdiv(P1_IM2COL + P1_WPAD, 256), 256>>>(
        x, lo, hi, w1, P0, P1, P2, WP);

    // (2) conv1: -> [16,96,15,15] RAW sums  (Fp=148, small smem, 4+ blocks/SM)
    normdist_conv_t<148, 0, 4><<<dim3(24, 450), 256, 4 * 148 * 4>>>(
        P0, P1, P2, WP, A0, A1, A2, 225, 96);

    // (3) pool1 (max on raw sums, then root8): -> (c,m,r) [16,96,7,7]
    pool3s_kernel<<<cdiv(16 * 96 * 49, 256), 256>>>(
        A0, A1, A2, B0, B1, B2, 16 * 96, 15, 15, 7, 7);

    // (4) gather k=5,p=2: Fp=2400
    gather_t_kernel<96, 7, 5, 2><<<cdiv(16 * 49 * 2400, 256), 256>>>(
        B0, B1, B2, P0, P1, P2);

    // (5) conv2: -> [16,256,7,7] RAW sums
    normdist_conv_t<2400, 0, 3><<<dim3(64, 98), 256, 4 * 2400 * 4>>>(
        P0, P1, P2, w2, A0, A1, A2, 49, 256);

    // (6) pool2: -> (c,m,r) [16,256,3,3]
    pool3s_kernel<<<cdiv(16 * 256 * 9, 256), 256>>>(
        A0, A1, A2, B0, B1, B2, 16 * 256, 7, 7, 3, 3);

    // (7) gather k=3,p=1: Fp=2304
    gather_t_kernel<256, 3, 3, 1><<<cdiv(16 * 9 * 2304, 256), 256>>>(
        B0, B1, B2, P0, P1, P2);

    // (8) conv3: -> [16,384,3,3] as (c,m,r)
    normdist_conv_t<2304, 1, 3><<<dim3(96, 18), 256, 4 * 2304 * 4>>>(
        P0, P1, P2, w3, A0, A1, A2, 9, 384);

    // (9) gather k=3,p=1: Fp=3456
    gather_t_kernel<384, 3, 3, 1><<<cdiv(16 * 9 * 3456, 256), 256>>>(
        A0, A1, A2, P0, P1, P2);

    // (10) conv4: -> [16,384,3,3] as (c,m,r)
    normdist_conv_t<3456, 1, 3><<<dim3(96, 18), 256, 4 * 3456 * 4>>>(
        P0, P1, P2, w4, B0, B1, B2, 9, 384);

    // (11) gather: Fp=3456
    gather_t_kernel<384, 3, 3, 1><<<cdiv(16 * 9 * 3456, 256), 256>>>(
        B0, B1, B2, P0, P1, P2);

    // (12) conv5: -> [16,256,3,3] as (c,m,r) == flattened [16,2304]
    normdist_conv_t<3456, 1, 3><<<dim3(64, 18), 256, 4 * 3456 * 4>>>(
        P0, P1, P2, w5, A0, A1, A2, 9, 256);

    // (13) fc1: 2304 -> 1024 (+relu), (c,m,r)
    bound_linear4_kernel<<<cdiv(1024 * 4 * 32, 256), 256>>>(
        A0, A1, A2, fw1, (const float*)nullptr, B0, B1, B2, 16, 2304, 1024, 0);
    // (14) fc2: 1024 -> 512 (+relu)
    bound_linear4_kernel<<<cdiv(512 * 4 * 32, 256), 256>>>(
        B0, B1, B2, fw2, (const float*)nullptr, A0, A1, A2, 16, 1024, 512, 0);
    // (15) fc3: 512 -> 10 (+bias): d_out = [-c | -u | -l]
    bound_linear4_kernel<<<cdiv(10 * 4 * 32, 256), 256>>>(
        A0, A1, A2, fw3, fb3, out, out + 160, out + 320, 16, 512, 10, 1);
}